// round 10
// baseline (speedup 1.0000x reference)
#include <cuda_runtime.h>
#include <cuda_bf16.h>
#include <cuda_fp16.h>
#include <math.h>
#include <stdint.h>

#define NN 50000
#define NE 800000
#define NODE_F 128
#define EDGE_F 32
#define TIME_D 16
#define K1 176
#define DN 128

typedef unsigned long long ull;

// ---------------- scratch ----------------
__device__ float g_agg[(size_t)NN * 128];
__device__ float g_cnt[NN];
__device__ uint32_t g_yf16[(size_t)NN * 64];       // Y = x @ W1x, f16x2 packed
__device__ uint32_t g_tf16[(size_t)NE * 24];       // tail (attr|time) f16x2, 48 vals

// ---------------- helpers ----------------
__device__ __forceinline__ uint32_t smem_u32(const void* p) {
    uint32_t a;
    asm("{ .reg .u64 t; cvta.to.shared.u64 t, %1; cvt.u32.u64 %0, t; }" : "=r"(a) : "l"(p));
    return a;
}
__device__ __forceinline__ float sigm(float x) { return 1.0f / (1.0f + expf(-x)); }

__device__ __forceinline__ uint32_t h2u(float a, float b) {
    __half2 h = __floats2half2_rn(a, b);
    return *reinterpret_cast<uint32_t*>(&h);
}
__device__ __forceinline__ void fsplit(float v, __half& h, __half& l) {
    h = __float2half_rn(v);
    l = __float2half_rn(v - __half2float(h));
}

__device__ __forceinline__ void ldsm_x4(uint32_t& r0, uint32_t& r1, uint32_t& r2, uint32_t& r3,
                                        uint32_t addr) {
    asm volatile("ldmatrix.sync.aligned.m8n8.x4.shared.b16 {%0,%1,%2,%3}, [%4];"
                 : "=r"(r0), "=r"(r1), "=r"(r2), "=r"(r3) : "r"(addr));
}
__device__ __forceinline__ void mma_f16(float* d, const uint32_t* a, const uint32_t* b) {
    asm volatile("mma.sync.aligned.m16n8k16.row.col.f32.f16.f16.f32 "
                 "{%0,%1,%2,%3}, {%4,%5,%6,%7}, {%8,%9}, {%0,%1,%2,%3};"
                 : "+f"(d[0]), "+f"(d[1]), "+f"(d[2]), "+f"(d[3])
                 : "r"(a[0]), "r"(a[1]), "r"(a[2]), "r"(a[3]), "r"(b[0]), "r"(b[1]));
}
__device__ __forceinline__ void cp16(uint32_t s, const void* g) {
    asm volatile("cp.async.ca.shared.global [%0], [%1], 16;" :: "r"(s), "l"(g));
}
#define CP_COMMIT() asm volatile("cp.async.commit_group;" ::: "memory")
#define CP_WAIT1()  asm volatile("cp.async.wait_group 1;" ::: "memory")
#define GBAR(id)    asm volatile("bar.sync %0, 128;" :: "r"(id) : "memory")

// ---------------- zero scratch ----------------
__global__ void zero_kernel() {
    int i = blockIdx.x * blockDim.x + threadIdx.x;
    int stride = gridDim.x * blockDim.x;
    float4 z = make_float4(0.f, 0.f, 0.f, 0.f);
    float4* a4 = reinterpret_cast<float4*>(g_agg);
    for (int j = i; j < NN * 128 / 4; j += stride) a4[j] = z;
    for (int j = i; j < NN; j += stride) g_cnt[j] = 0.f;
}

// ---------------- precompute: per-edge tail + cnt ----------------
__global__ void edge_pre_kernel(const float* __restrict__ eattr, const float* __restrict__ tt,
                                const float* __restrict__ tw, const float* __restrict__ tb,
                                const int* __restrict__ ei) {
    int e = blockIdx.x * blockDim.x + threadIdx.x;
    if (e >= NE) return;
    uint32_t th[24];
    const float4* er = (const float4*)(eattr + (size_t)e * 32);
#pragma unroll
    for (int i = 0; i < 8; ++i) {
        float4 f = __ldg(&er[i]);
        th[2 * i]     = h2u(f.x, f.y);
        th[2 * i + 1] = h2u(f.z, f.w);
    }
    float tv = __ldg(&tt[e]);
#pragma unroll
    for (int d = 0; d < 8; ++d) {
        float a = cosf(tv * __ldg(&tw[2 * d])     + __ldg(&tb[2 * d]));
        float b = cosf(tv * __ldg(&tw[2 * d + 1]) + __ldg(&tb[2 * d + 1]));
        th[16 + d] = h2u(a, b);
    }
    uint4* dh = (uint4*)(g_tf16 + (size_t)e * 24);
#pragma unroll
    for (int q = 0; q < 6; ++q)
        dh[q] = make_uint4(th[4 * q], th[4 * q + 1], th[4 * q + 2], th[4 * q + 3]);
    atomicAdd(&g_cnt[__ldg(&ei[NE + e])], 1.0f);
}

// ================= Y KERNEL: Y = x @ W1[0:128,:] (f16) =================
#define YW 0          // [128][136] f16 = 34816
#define YA 34816      // [64][136]  f16 = 17408
#define Y_SMEM_BYTES 52352

__global__ __launch_bounds__(256)
void y_kernel(const float* __restrict__ x, const float* __restrict__ w1) {
    extern __shared__ char smc[];
    const uint32_t smb = smem_u32(smc);
    const int tid = threadIdx.x, wid = tid >> 5, lane = tid & 31;
    const int m0 = (wid & 3) * 16, nbase = (wid >> 2) * 64;
    const int base = blockIdx.x * 64;
    const int crow = lane >> 2, ccol = (lane & 3) * 2;

    // stage W1x [n][k]
    for (int idx = tid; idx < 128 * 128; idx += 256) {
        int k = idx >> 7, n = idx & 127;
        *(__half*)(smc + YW + 2 * (n * 136 + k)) = __float2half_rn(w1[k * 128 + n]);
    }
    // stage A = x rows (f16)
    for (int idx = tid; idx < 64 * 64; idx += 256) {
        int m = idx >> 6, kp = idx & 63;
        int row = base + m;
        uint32_t v = 0u;
        if (row < NN)
            v = h2u(__ldg(&x[(size_t)row * 128 + 2 * kp]),
                    __ldg(&x[(size_t)row * 128 + 2 * kp + 1]));
        *(uint32_t*)(smc + YA + 2 * (m * 136 + 2 * kp)) = v;
    }
    __syncthreads();

    const uint32_t aRow = (uint32_t)((m0 + (lane & 15)) * 136 + ((lane >> 4) << 3)) * 2;
    const uint32_t bRow = (uint32_t)((lane & 7) + ((lane >> 4) << 3));
    const uint32_t bLane = (uint32_t)(bRow * 136 + (((lane >> 3) & 1) << 3)) * 2;

    float acc[8][4];
#pragma unroll
    for (int j = 0; j < 8; ++j)
#pragma unroll
        for (int q = 0; q < 4; ++q) acc[j][q] = 0.f;

#pragma unroll
    for (int ks = 0; ks < 8; ++ks) {
        const uint32_t kOff = (uint32_t)(ks * 16) * 2;
        uint32_t a[4];
        ldsm_x4(a[0], a[1], a[2], a[3], smb + YA + aRow + kOff);
#pragma unroll
        for (int jj = 0; jj < 4; ++jj) {
            const uint32_t nOff = (uint32_t)((nbase + jj * 16) * 136) * 2;
            uint32_t b[4];
            ldsm_x4(b[0], b[1], b[2], b[3], smb + YW + bLane + nOff + kOff);
            mma_f16(acc[2 * jj],     a, b);
            mma_f16(acc[2 * jj + 1], a, b + 2);
        }
    }

    int r0 = m0 + crow, r1 = r0 + 8;
    int nd0 = base + r0, nd1 = base + r1;
#pragma unroll
    for (int j = 0; j < 8; ++j) {
        int c = (nbase + j * 8 + ccol) >> 1;
        if (nd0 < NN) g_yf16[(size_t)nd0 * 64 + c] = h2u(acc[j][0], acc[j][1]);
        if (nd1 < NN) g_yf16[(size_t)nd1 * 64 + c] = h2u(acc[j][2], acc[j][3]);
    }
}

// ================= EDGE KERNEL (factored GEMM1, 3 pipeline groups) =================
#define EK_M   32
#define NT32   (NE / EK_M)
#define NGRP   3
#define LDAT   56          // tail A stride (f16)
#define LDH    136
#define AT_BYTES 3584      // 32*56*2

// smem byte offsets
#define SM_W1T 0           // [128][56] f16 = 14336
#define SM_W2  14336       // [128][136] f16 = 34816
#define SM_H   49152       // 3 * 8704 = 26112
#define SM_A   75264       // 6 * 3584 = 21504  (grp*2+buf)
#define SM_B1  96768
#define SM_B2  97280
#define SM_TGT 97792       // 6 * 32 ints = 768
#define SM_SRC 98560       // 768
#define EDGE_SMEM_BYTES 99328

__device__ __forceinline__ void prefetch_tile(int tile, uint32_t aBase, int* tgtS, int* srcS,
                                              const int* __restrict__ ei, int gt) {
    const int e = gt >> 2, sub = gt & 3;
    const int ge = tile * EK_M + e;
    const char* tf = (const char*)g_tf16 + (size_t)ge * 96;
    const uint32_t arow = aBase + (uint32_t)e * (LDAT * 2);
#pragma unroll
    for (int c = sub; c < 6; c += 4) cp16(arow + c * 16, tf + c * 16);
    if (sub == 0) tgtS[e] = __ldg(&ei[NE + ge]);
    if (sub == 1) srcS[e] = __ldg(&ei[ge]);
}

__global__ __launch_bounds__(384, 1)
void edge_kernel(const float* __restrict__ w1, const float* __restrict__ b1,
                 const float* __restrict__ w2, const float* __restrict__ b2,
                 const int* __restrict__ ei)
{
    extern __shared__ char smc[];
    const uint32_t smb = smem_u32(smc);
    const int tid = threadIdx.x;
    const int wid = tid >> 5, lane = tid & 31;
    const int grp = wid >> 2;            // pipeline group 0..2
    const int gw = wid & 3;              // warp within group (one per SMSP)
    const int nbase = gw * 32;           // 32-col slice per warp
    const int gt = tid & 127;

    float* b1s = (float*)(smc + SM_B1);
    float* b2s = (float*)(smc + SM_B2);

    // ---- stage weights ----
    for (int idx = tid; idx < 48 * DN; idx += 384) {
        int k = idx >> 7, n = idx & 127;
        *(__half*)(smc + SM_W1T + 2 * (n * LDAT + k)) = __float2half_rn(w1[(128 + k) * 128 + n]);
    }
    for (int idx = tid; idx < DN * DN; idx += 384) {
        int k = idx >> 7, n = idx & 127;
        *(__half*)(smc + SM_W2 + 2 * (n * LDH + k)) = __float2half_rn(w2[idx]);
    }
    for (int i = tid; i < 128; i += 384) { b1s[i] = b1[i]; b2s[i] = b2[i]; }
    __syncthreads();

    const int barId = 1 + grp;
    const uint32_t hBase = smb + SM_H + grp * 8704;

    // fragment lane addressing (bytes)
    const uint32_t aRow0T = (uint32_t)((lane & 15) * LDAT + ((lane >> 4) << 3)) * 2;
    const uint32_t aRow1T = aRow0T + (uint32_t)(16 * LDAT) * 2;
    const uint32_t hRow0 = (uint32_t)((lane & 15) * LDH + ((lane >> 4) << 3)) * 2;
    const uint32_t hRow1 = hRow0 + (uint32_t)(16 * LDH) * 2;
    const uint32_t bRow = (uint32_t)((lane & 7) + ((lane >> 4) << 3));
    const uint32_t bColPiece = (uint32_t)(((lane >> 3) & 1) << 3);
    const uint32_t b1LaneOff = (uint32_t)(bRow * LDAT + bColPiece) * 2;
    const uint32_t b2LaneOff = (uint32_t)(bRow * LDH + bColPiece) * 2;
    const int crow = lane >> 2;
    const int ccol = (lane & 3) * 2;

    int buf = 0;
    int tile = blockIdx.x * NGRP + grp;
    const int step = gridDim.x * NGRP;

    if (tile < NT32)
        prefetch_tile(tile, smb + SM_A + (uint32_t)(grp * 2 + buf) * AT_BYTES,
                      (int*)(smc + SM_TGT) + (grp * 2 + buf) * 32,
                      (int*)(smc + SM_SRC) + (grp * 2 + buf) * 32, ei, gt);
    CP_COMMIT();

    for (; tile < NT32; tile += step) {
        const int nxt = tile + step;
        if (nxt < NT32)
            prefetch_tile(nxt, smb + SM_A + (uint32_t)(grp * 2 + (buf ^ 1)) * AT_BYTES,
                          (int*)(smc + SM_TGT) + (grp * 2 + (buf ^ 1)) * 32,
                          (int*)(smc + SM_SRC) + (grp * 2 + (buf ^ 1)) * 32, ei, gt);
        CP_COMMIT();
        CP_WAIT1();
        GBAR(barId);

        const uint32_t aBase = smb + SM_A + (uint32_t)(grp * 2 + buf) * AT_BYTES;
        int* tgts = (int*)(smc + SM_TGT) + (grp * 2 + buf) * 32;
        int* srcs = (int*)(smc + SM_SRC) + (grp * 2 + buf) * 32;

        // ---- issue Y gather early (consumed in epilogue 1) ----
        int s0 = srcs[crow],      s1 = srcs[crow + 8];
        int s2 = srcs[16 + crow], s3 = srcs[24 + crow];
        uint32_t yv[16];
#pragma unroll
        for (int j = 0; j < 4; ++j) {
            int c = (nbase + j * 8 + ccol) >> 1;
            yv[0 * 4 + j] = __ldg(&g_yf16[(size_t)s0 * 64 + c]);
            yv[1 * 4 + j] = __ldg(&g_yf16[(size_t)s1 * 64 + c]);
            yv[2 * 4 + j] = __ldg(&g_yf16[(size_t)s2 * 64 + c]);
            yv[3 * 4 + j] = __ldg(&g_yf16[(size_t)s3 * 64 + c]);
        }

        // acc[mf][piece][quad]
        float acc[2][4][4];
#pragma unroll
        for (int i = 0; i < 2; ++i)
#pragma unroll
            for (int j = 0; j < 4; ++j)
#pragma unroll
                for (int q = 0; q < 4; ++q) acc[i][j][q] = 0.f;

        // ---------- GEMM1': tail[32,48] @ W1t ----------
#pragma unroll
        for (int ks = 0; ks < 3; ++ks) {
            const uint32_t kOff = (uint32_t)(ks * 16) * 2;
            uint32_t a0[4], a1[4];
            ldsm_x4(a0[0], a0[1], a0[2], a0[3], aBase + aRow0T + kOff);
            ldsm_x4(a1[0], a1[1], a1[2], a1[3], aBase + aRow1T + kOff);
#pragma unroll
            for (int jj = 0; jj < 2; ++jj) {
                const uint32_t nOff = (uint32_t)((nbase + jj * 16) * LDAT) * 2;
                uint32_t b[4];
                ldsm_x4(b[0], b[1], b[2], b[3], smb + SM_W1T + b1LaneOff + nOff + kOff);
                mma_f16(acc[0][jj * 2],     a0, b);
                mma_f16(acc[0][jj * 2 + 1], a0, b + 2);
                mma_f16(acc[1][jj * 2],     a1, b);
                mma_f16(acc[1][jj * 2 + 1], a1, b + 2);
            }
        }

        // ---------- epilogue 1: relu(acc + Y + b1) -> H (f16) ----------
#pragma unroll
        for (int mf = 0; mf < 2; ++mf) {
            int r0 = mf * 16 + crow, r1 = r0 + 8;
#pragma unroll
            for (int j = 0; j < 4; ++j) {
                int n = nbase + j * 8 + ccol;
                __half2 y0 = *reinterpret_cast<__half2*>(&yv[(mf * 2 + 0) * 4 + j]);
                __half2 y1 = *reinterpret_cast<__half2*>(&yv[(mf * 2 + 1) * 4 + j]);
                float v0 = fmaxf(acc[mf][j][0] + __low2float(y0)  + b1s[n],     0.f);
                float v1 = fmaxf(acc[mf][j][1] + __high2float(y0) + b1s[n + 1], 0.f);
                float v2 = fmaxf(acc[mf][j][2] + __low2float(y1)  + b1s[n],     0.f);
                float v3 = fmaxf(acc[mf][j][3] + __high2float(y1) + b1s[n + 1], 0.f);
                *(__half2*)(smc + (hBase - smb) + 2 * (r0 * LDH + n)) = __floats2half2_rn(v0, v1);
                *(__half2*)(smc + (hBase - smb) + 2 * (r1 * LDH + n)) = __floats2half2_rn(v2, v3);
            }
        }
        GBAR(barId);

        // ---------- GEMM2: D2 = H(128) @ W2 ----------
#pragma unroll
        for (int i = 0; i < 2; ++i)
#pragma unroll
            for (int j = 0; j < 4; ++j)
#pragma unroll
                for (int q = 0; q < 4; ++q) acc[i][j][q] = 0.f;

#pragma unroll
        for (int ks = 0; ks < 8; ++ks) {
            const uint32_t kOff = (uint32_t)(ks * 16) * 2;
            uint32_t a0[4], a1[4];
            ldsm_x4(a0[0], a0[1], a0[2], a0[3], hBase + hRow0 + kOff);
            ldsm_x4(a1[0], a1[1], a1[2], a1[3], hBase + hRow1 + kOff);
#pragma unroll
            for (int jj = 0; jj < 2; ++jj) {
                const uint32_t nOff = (uint32_t)((nbase + jj * 16) * LDH) * 2;
                uint32_t b[4];
                ldsm_x4(b[0], b[1], b[2], b[3], smb + SM_W2 + b2LaneOff + nOff + kOff);
                mma_f16(acc[0][jj * 2],     a0, b);
                mma_f16(acc[0][jj * 2 + 1], a0, b + 2);
                mma_f16(acc[1][jj * 2],     a1, b);
                mma_f16(acc[1][jj * 2 + 1], a1, b + 2);
            }
        }

        // ---------- epilogue 2: scatter ----------
#pragma unroll
        for (int mf = 0; mf < 2; ++mf) {
            int tg0 = tgts[mf * 16 + crow];
            int tg1 = tgts[mf * 16 + crow + 8];
            size_t ga0 = __cvta_generic_to_global(&g_agg[(size_t)tg0 * 128]);
            size_t ga1 = __cvta_generic_to_global(&g_agg[(size_t)tg1 * 128]);
#pragma unroll
            for (int j = 0; j < 4; ++j) {
                int n = nbase + j * 8 + ccol;
                float v0 = acc[mf][j][0] + b2s[n];
                float v1 = acc[mf][j][1] + b2s[n + 1];
                float v2 = acc[mf][j][2] + b2s[n];
                float v3 = acc[mf][j][3] + b2s[n + 1];
                asm volatile("red.global.add.v2.f32 [%0], {%1,%2};"
                             :: "l"(ga0 + (size_t)n * 4), "f"(v0), "f"(v1) : "memory");
                asm volatile("red.global.add.v2.f32 [%0], {%1,%2};"
                             :: "l"(ga1 + (size_t)n * 4), "f"(v2), "f"(v3) : "memory");
            }
        }
        GBAR(barId);
        buf ^= 1;
    }
}

// ================= NODE KERNEL (f16 hybrid hi/lo) =================
#define NLDB 136
#define NB_HI 0
#define NB_LO 34816
#define NVS   69632
#define NMS   87040
#define NODE_SMEM_BYTES 104448

__device__ __forceinline__ void hgemm_128(uint32_t smb, uint32_t aAddr,
                                          uint32_t bHiOff, uint32_t bLoOff,
                                          uint32_t bLaneOff, int nbase, float acc[8][4]) {
#pragma unroll
    for (int j = 0; j < 8; ++j)
#pragma unroll
        for (int q = 0; q < 4; ++q) acc[j][q] = 0.f;
#pragma unroll
    for (int ks = 0; ks < 8; ++ks) {
        const uint32_t kOff = (uint32_t)(ks * 16) * 2;
        uint32_t a[4];
        ldsm_x4(a[0], a[1], a[2], a[3], aAddr + kOff);
#pragma unroll
        for (int jj = 0; jj < 4; ++jj) {
            const uint32_t nOff = (uint32_t)((nbase + jj * 16) * NLDB) * 2;
            uint32_t bh[4], bl[4];
            ldsm_x4(bh[0], bh[1], bh[2], bh[3], smb + bHiOff + bLaneOff + nOff + kOff);
            ldsm_x4(bl[0], bl[1], bl[2], bl[3], smb + bLoOff + bLaneOff + nOff + kOff);
            mma_f16(acc[2 * jj],     a, bh);
            mma_f16(acc[2 * jj + 1], a, bh + 2);
            mma_f16(acc[2 * jj],     a, bl);
            mma_f16(acc[2 * jj + 1], a, bl + 2);
        }
    }
}

__device__ __forceinline__ void node_stageB(char* smc, const float* __restrict__ src, int tid) {
    for (int idx = tid; idx < 128 * 64; idx += 256) {
        int n = idx >> 6, kp = idx & 63;
        float v0 = __ldg(&src[n * 128 + 2 * kp]);
        float v1 = __ldg(&src[n * 128 + 2 * kp + 1]);
        __half h0, l0, h1, l1;
        fsplit(v0, h0, l0);
        fsplit(v1, h1, l1);
        *(__half2*)(smc + NB_HI + 2 * (n * NLDB + 2 * kp)) = __halves2half2(h0, h1);
        *(__half2*)(smc + NB_LO + 2 * (n * NLDB + 2 * kp)) = __halves2half2(l0, l1);
    }
}

__global__ __launch_bounds__(256)
void node_kernel(const float* __restrict__ wih, const float* __restrict__ bih,
                 const float* __restrict__ bhh, const float* __restrict__ ow,
                 const float* __restrict__ ob, float* __restrict__ out)
{
    extern __shared__ char smc[];
    const uint32_t smb = smem_u32(smc);
    const int tid = threadIdx.x, wid = tid >> 5, lane = tid & 31;
    const int m0 = (wid & 3) * 16, nbase = (wid >> 2) * 64;
    const int base = blockIdx.x * 64;
    const int crow = lane >> 2, ccol = (lane & 3) * 2;

    for (int idx = tid; idx < 64 * 64; idx += 256) {
        int m = idx >> 6, kp = idx & 63;
        int nd = base + m;
        float a0 = 0.f, a1 = 0.f;
        if (nd < NN) {
            float inv = 1.0f / fmaxf(g_cnt[nd], 1.0f);
            a0 = g_agg[(size_t)nd * 128 + 2 * kp] * inv;
            a1 = g_agg[(size_t)nd * 128 + 2 * kp + 1] * inv;
        }
        *(__half2*)(smc + NVS + 2 * (m * NLDB + 2 * kp)) = __floats2half2_rn(a0, a1);
    }

    const uint32_t aRow = (uint32_t)((m0 + (lane & 15)) * NLDB + ((lane >> 4) << 3)) * 2;
    const uint32_t bRow = (uint32_t)((lane & 7) + ((lane >> 4) << 3));
    const uint32_t bLane = (uint32_t)(bRow * NLDB + (((lane >> 3) & 1) << 3)) * 2;

    float acc[8][4], rg[8][4], ng[8][4];

    node_stageB(smc, wih, tid);
    __syncthreads();
    hgemm_128(smb, smb + NVS + aRow, NB_HI, NB_LO, bLane, nbase, acc);
#pragma unroll
    for (int j = 0; j < 8; ++j) {
        int n = nbase + j * 8 + ccol;
        rg[j][0] = sigm(acc[j][0] + __ldg(&bih[n])     + __ldg(&bhh[n]));
        rg[j][1] = sigm(acc[j][1] + __ldg(&bih[n + 1]) + __ldg(&bhh[n + 1]));
        rg[j][2] = sigm(acc[j][2] + __ldg(&bih[n])     + __ldg(&bhh[n]));
        rg[j][3] = sigm(acc[j][3] + __ldg(&bih[n + 1]) + __ldg(&bhh[n + 1]));
    }
    __syncthreads();

    node_stageB(smc, wih + 2 * 128 * 128, tid);
    __syncthreads();
    hgemm_128(smb, smb + NVS + aRow, NB_HI, NB_LO, bLane, nbase, acc);
#pragma unroll
    for (int j = 0; j < 8; ++j) {
        int n = 256 + nbase + j * 8 + ccol;
        ng[j][0] = tanhf(acc[j][0] + __ldg(&bih[n])     + rg[j][0] * __ldg(&bhh[n]));
        ng[j][1] = tanhf(acc[j][1] + __ldg(&bih[n + 1]) + rg[j][1] * __ldg(&bhh[n + 1]));
        ng[j][2] = tanhf(acc[j][2] + __ldg(&bih[n])     + rg[j][2] * __ldg(&bhh[n]));
        ng[j][3] = tanhf(acc[j][3] + __ldg(&bih[n + 1]) + rg[j][3] * __ldg(&bhh[n + 1]));
    }
    __syncthreads();

    node_stageB(smc, wih + 1 * 128 * 128, tid);
    __syncthreads();
    hgemm_128(smb, smb + NVS + aRow, NB_HI, NB_LO, bLane, nbase, acc);
    {
        int r0 = m0 + crow, r1 = m0 + crow + 8;
#pragma unroll
        for (int j = 0; j < 8; ++j) {
            int nl = nbase + j * 8 + ccol;
            int n = 128 + nl;
            float z0 = sigm(acc[j][0] + __ldg(&bih[n])     + __ldg(&bhh[n]));
            float z1 = sigm(acc[j][1] + __ldg(&bih[n + 1]) + __ldg(&bhh[n + 1]));
            float z2 = sigm(acc[j][2] + __ldg(&bih[n])     + __ldg(&bhh[n]));
            float z3 = sigm(acc[j][3] + __ldg(&bih[n + 1]) + __ldg(&bhh[n + 1]));
            float m0v = (1.f - z0) * ng[j][0];
            float m1v = (1.f - z1) * ng[j][1];
            float m2v = (1.f - z2) * ng[j][2];
            float m3v = (1.f - z3) * ng[j][3];
            *(__half2*)(smc + NMS + 2 * (r0 * NLDB + nl)) = __floats2half2_rn(m0v, m1v);
            *(__half2*)(smc + NMS + 2 * (r1 * NLDB + nl)) = __floats2half2_rn(m2v, m3v);
        }
    }
    __syncthreads();

    node_stageB(smc, ow, tid);
    __syncthreads();
    hgemm_128(smb, smb + NMS + aRow, NB_HI, NB_LO, bLane, nbase, acc);
    {
        int r0 = m0 + crow, r1 = m0 + crow + 8;
        int nd0 = base + r0, nd1 = base + r1;
#pragma unroll
        for (int j = 0; j < 8; ++j) {
            int n = nbase + j * 8 + ccol;
            float o0 = __ldg(&ob[n]), o1 = __ldg(&ob[n + 1]);
            if (nd0 < NN)
                *(float2*)&out[(size_t)nd0 * 128 + n] = make_float2(acc[j][0] + o0, acc[j][1] + o1);
            if (nd1 < NN)
                *(float2*)&out[(size_t)nd1 * 128 + n] = make_float2(acc[j][2] + o0, acc[j][3] + o1);
        }
    }
}

// ================= launch =================
extern "C" void kernel_launch(void* const* d_in, const int* in_sizes, int n_in,
                              void* d_out, int out_size) {
    const float* x     = (const float*)d_in[0];
    const float* eattr = (const float*)d_in[1];
    const float* t     = (const float*)d_in[2];
    const float* tw    = (const float*)d_in[3];
    const float* tb    = (const float*)d_in[4];
    const float* w1    = (const float*)d_in[5];
    const float* b1    = (const float*)d_in[6];
    const float* w2    = (const float*)d_in[7];
    const float* b2    = (const float*)d_in[8];
    const float* wih   = (const float*)d_in[9];
    const float* bih   = (const float*)d_in[11];
    const float* bhh   = (const float*)d_in[12];
    const float* ow    = (const float*)d_in[13];
    const float* ob    = (const float*)d_in[14];
    const int*   ei    = (const int*)d_in[15];
    float* out = (float*)d_out;

    cudaFuncSetAttribute(edge_kernel, cudaFuncAttributeMaxDynamicSharedMemorySize, EDGE_SMEM_BYTES);
    cudaFuncSetAttribute(node_kernel, cudaFuncAttributeMaxDynamicSharedMemorySize, NODE_SMEM_BYTES);
    cudaFuncSetAttribute(y_kernel,    cudaFuncAttributeMaxDynamicSharedMemorySize, Y_SMEM_BYTES);

    zero_kernel<<<256, 256>>>();
    edge_pre_kernel<<<(NE + 255) / 256, 256>>>(eattr, t, tw, tb, ei);
    y_kernel<<<(NN + 63) / 64, 256, Y_SMEM_BYTES>>>(x, w1);
    edge_kernel<<<148, 384, EDGE_SMEM_BYTES>>>(w1, b1, w2, b2, ei);
    node_kernel<<<(NN + 63) / 64, 256, NODE_SMEM_BYTES>>>(wih, bih, bhh, ow, ob, out);
}

// round 11
// speedup vs baseline: 1.0533x; 1.0533x over previous
#include <cuda_runtime.h>
#include <cuda_bf16.h>
#include <cuda_fp16.h>
#include <math.h>
#include <stdint.h>

#define NN 50000
#define NE 800000
#define NODE_F 128
#define EDGE_F 32
#define TIME_D 16
#define K1 176
#define DN 128

typedef unsigned long long ull;

// ---------------- scratch ----------------
__device__ float g_agg[(size_t)NN * 128];
__device__ float g_cnt[NN];
__device__ uint32_t g_yf16[(size_t)NN * 64];       // Y = x @ W1x, f16x2 packed
__device__ uint32_t g_tf16[(size_t)NE * 24];       // tail (attr|time) f16x2, 48 vals

// ---------------- helpers ----------------
__device__ __forceinline__ uint32_t smem_u32(const void* p) {
    uint32_t a;
    asm("{ .reg .u64 t; cvta.to.shared.u64 t, %1; cvt.u32.u64 %0, t; }" : "=r"(a) : "l"(p));
    return a;
}
__device__ __forceinline__ float sigm(float x) { return 1.0f / (1.0f + expf(-x)); }

__device__ __forceinline__ uint32_t h2u(float a, float b) {
    __half2 h = __floats2half2_rn(a, b);
    return *reinterpret_cast<uint32_t*>(&h);
}

__device__ __forceinline__ void ldsm_x4(uint32_t& r0, uint32_t& r1, uint32_t& r2, uint32_t& r3,
                                        uint32_t addr) {
    asm volatile("ldmatrix.sync.aligned.m8n8.x4.shared.b16 {%0,%1,%2,%3}, [%4];"
                 : "=r"(r0), "=r"(r1), "=r"(r2), "=r"(r3) : "r"(addr));
}
__device__ __forceinline__ void mma_f16(float* d, const uint32_t* a, const uint32_t* b) {
    asm volatile("mma.sync.aligned.m16n8k16.row.col.f32.f16.f16.f32 "
                 "{%0,%1,%2,%3}, {%4,%5,%6,%7}, {%8,%9}, {%0,%1,%2,%3};"
                 : "+f"(d[0]), "+f"(d[1]), "+f"(d[2]), "+f"(d[3])
                 : "r"(a[0]), "r"(a[1]), "r"(a[2]), "r"(a[3]), "r"(b[0]), "r"(b[1]));
}
#define GBAR(id)    asm volatile("bar.sync %0, 128;" :: "r"(id) : "memory")

// ---------------- zero scratch ----------------
__global__ void zero_kernel() {
    int i = blockIdx.x * blockDim.x + threadIdx.x;
    int stride = gridDim.x * blockDim.x;
    float4 z = make_float4(0.f, 0.f, 0.f, 0.f);
    float4* a4 = reinterpret_cast<float4*>(g_agg);
    for (int j = i; j < NN * 128 / 4; j += stride) a4[j] = z;
    for (int j = i; j < NN; j += stride) g_cnt[j] = 0.f;
}

// ---------------- precompute: per-edge tail + cnt ----------------
__global__ void edge_pre_kernel(const float* __restrict__ eattr, const float* __restrict__ tt,
                                const float* __restrict__ tw, const float* __restrict__ tb,
                                const int* __restrict__ ei) {
    int e = blockIdx.x * blockDim.x + threadIdx.x;
    if (e >= NE) return;
    uint32_t th[24];
    const float4* er = (const float4*)(eattr + (size_t)e * 32);
#pragma unroll
    for (int i = 0; i < 8; ++i) {
        float4 f = __ldg(&er[i]);
        th[2 * i]     = h2u(f.x, f.y);
        th[2 * i + 1] = h2u(f.z, f.w);
    }
    float tv = __ldg(&tt[e]);
#pragma unroll
    for (int d = 0; d < 8; ++d) {
        float a = cosf(tv * __ldg(&tw[2 * d])     + __ldg(&tb[2 * d]));
        float b = cosf(tv * __ldg(&tw[2 * d + 1]) + __ldg(&tb[2 * d + 1]));
        th[16 + d] = h2u(a, b);
    }
    uint4* dh = (uint4*)(g_tf16 + (size_t)e * 24);
#pragma unroll
    for (int q = 0; q < 6; ++q)
        dh[q] = make_uint4(th[4 * q], th[4 * q + 1], th[4 * q + 2], th[4 * q + 3]);
    atomicAdd(&g_cnt[__ldg(&ei[NE + e])], 1.0f);
}

// ================= Y KERNEL: Y = x @ W1[0:128,:] (f16) =================
#define YW 0          // [128][136] f16 = 34816
#define YA 34816      // [64][136]  f16 = 17408
#define Y_SMEM_BYTES 52352

__global__ __launch_bounds__(256)
void y_kernel(const float* __restrict__ x, const float* __restrict__ w1) {
    extern __shared__ char smc[];
    const uint32_t smb = smem_u32(smc);
    const int tid = threadIdx.x, wid = tid >> 5, lane = tid & 31;
    const int m0 = (wid & 3) * 16, nbase = (wid >> 2) * 64;
    const int base = blockIdx.x * 64;
    const int crow = lane >> 2, ccol = (lane & 3) * 2;

    for (int idx = tid; idx < 128 * 128; idx += 256) {
        int k = idx >> 7, n = idx & 127;
        *(__half*)(smc + YW + 2 * (n * 136 + k)) = __float2half_rn(w1[k * 128 + n]);
    }
    for (int idx = tid; idx < 64 * 64; idx += 256) {
        int m = idx >> 6, kp = idx & 63;
        int row = base + m;
        uint32_t v = 0u;
        if (row < NN)
            v = h2u(__ldg(&x[(size_t)row * 128 + 2 * kp]),
                    __ldg(&x[(size_t)row * 128 + 2 * kp + 1]));
        *(uint32_t*)(smc + YA + 2 * (m * 136 + 2 * kp)) = v;
    }
    __syncthreads();

    const uint32_t aRow = (uint32_t)((m0 + (lane & 15)) * 136 + ((lane >> 4) << 3)) * 2;
    const uint32_t bRow = (uint32_t)((lane & 7) + ((lane >> 4) << 3));
    const uint32_t bLane = (uint32_t)(bRow * 136 + (((lane >> 3) & 1) << 3)) * 2;

    float acc[8][4];
#pragma unroll
    for (int j = 0; j < 8; ++j)
#pragma unroll
        for (int q = 0; q < 4; ++q) acc[j][q] = 0.f;

#pragma unroll
    for (int ks = 0; ks < 8; ++ks) {
        const uint32_t kOff = (uint32_t)(ks * 16) * 2;
        uint32_t a[4];
        ldsm_x4(a[0], a[1], a[2], a[3], smb + YA + aRow + kOff);
#pragma unroll
        for (int jj = 0; jj < 4; ++jj) {
            const uint32_t nOff = (uint32_t)((nbase + jj * 16) * 136) * 2;
            uint32_t b[4];
            ldsm_x4(b[0], b[1], b[2], b[3], smb + YW + bLane + nOff + kOff);
            mma_f16(acc[2 * jj],     a, b);
            mma_f16(acc[2 * jj + 1], a, b + 2);
        }
    }

    int r0 = m0 + crow, r1 = r0 + 8;
    int nd0 = base + r0, nd1 = base + r1;
#pragma unroll
    for (int j = 0; j < 8; ++j) {
        int c = (nbase + j * 8 + ccol) >> 1;
        if (nd0 < NN) g_yf16[(size_t)nd0 * 64 + c] = h2u(acc[j][0], acc[j][1]);
        if (nd1 < NN) g_yf16[(size_t)nd1 * 64 + c] = h2u(acc[j][2], acc[j][3]);
    }
}

// ================= EDGE KERNEL (register-resident tail, 3 groups) =================
#define EK_M   32
#define NT32   (NE / EK_M)
#define NGRP   3
#define LDAT   56
#define LDH    136

// smem byte offsets (no A buffers, no cp.async)
#define SM_W1T 0           // [128][56] f16 = 14336
#define SM_W2  14336       // [128][136] f16 = 34816
#define SM_H   49152       // 3 * 8704 = 26112
#define SM_B1  75264
#define SM_B2  75776
#define EDGE_SMEM_BYTES 76288

__global__ __launch_bounds__(384, 1)
void edge_kernel(const float* __restrict__ w1, const float* __restrict__ b1,
                 const float* __restrict__ w2, const float* __restrict__ b2,
                 const int* __restrict__ ei)
{
    extern __shared__ char smc[];
    const uint32_t smb = smem_u32(smc);
    const int tid = threadIdx.x;
    const int wid = tid >> 5, lane = tid & 31;
    const int grp = wid >> 2;            // pipeline group 0..2
    const int gw = wid & 3;
    const int nbase = gw * 32;

    float* b1s = (float*)(smc + SM_B1);
    float* b2s = (float*)(smc + SM_B2);

    // ---- stage weights ----
    for (int idx = tid; idx < 48 * DN; idx += 384) {
        int k = idx >> 7, n = idx & 127;
        *(__half*)(smc + SM_W1T + 2 * (n * LDAT + k)) = __float2half_rn(w1[(128 + k) * 128 + n]);
    }
    for (int idx = tid; idx < DN * DN; idx += 384) {
        int k = idx >> 7, n = idx & 127;
        *(__half*)(smc + SM_W2 + 2 * (n * LDH + k)) = __float2half_rn(w2[idx]);
    }
    for (int i = tid; i < 128; i += 384) { b1s[i] = b1[i]; b2s[i] = b2[i]; }
    __syncthreads();

    const int barId = 1 + grp;
    const uint32_t hBase = smb + SM_H + grp * 8704;

    const uint32_t hRow0 = (uint32_t)((lane & 15) * LDH + ((lane >> 4) << 3)) * 2;
    const uint32_t hRow1 = hRow0 + (uint32_t)(16 * LDH) * 2;
    const uint32_t bRow = (uint32_t)((lane & 7) + ((lane >> 4) << 3));
    const uint32_t bColPiece = (uint32_t)(((lane >> 3) & 1) << 3);
    const uint32_t b1LaneOff = (uint32_t)(bRow * LDAT + bColPiece) * 2;
    const uint32_t b2LaneOff = (uint32_t)(bRow * LDH + bColPiece) * 2;
    const int crow = lane >> 2;
    const int ccol = (lane & 3) * 2;
    const int kq = lane & 3;             // k-quad for tail A-frags

    int tile = blockIdx.x * NGRP + grp;
    const int step = gridDim.x * NGRP;

    // tail A-frags: [mf(2)][ks(3)][4 regs]  (direct-LDG fragment layout)
    uint32_t tailA[24], tailN[24];

    // preload first tile's tail frags
    {
        const uint32_t* tf = g_tf16 + (size_t)tile * EK_M * 24;
#pragma unroll
        for (int mf = 0; mf < 2; ++mf) {
            int e0 = (mf * 16 + crow) * 24;
            int e1 = e0 + 8 * 24;
#pragma unroll
            for (int ks = 0; ks < 3; ++ks) {
                int o = ks * 8 + kq;
                tailA[(mf * 3 + ks) * 4 + 0] = __ldg(&tf[e0 + o]);
                tailA[(mf * 3 + ks) * 4 + 1] = __ldg(&tf[e1 + o]);
                tailA[(mf * 3 + ks) * 4 + 2] = __ldg(&tf[e0 + o + 4]);
                tailA[(mf * 3 + ks) * 4 + 3] = __ldg(&tf[e1 + o + 4]);
            }
        }
    }

    for (; tile < NT32; tile += step) {
        const int ebase = tile * EK_M;

        // ---- srcs & tgts (quad-broadcast LDG) ----
        int s00 = __ldg(&ei[ebase + crow]);
        int s01 = __ldg(&ei[ebase + crow + 8]);
        int s10 = __ldg(&ei[ebase + 16 + crow]);
        int s11 = __ldg(&ei[ebase + 24 + crow]);
        int t00 = __ldg(&ei[NE + ebase + crow]);
        int t01 = __ldg(&ei[NE + ebase + crow + 8]);
        int t10 = __ldg(&ei[NE + ebase + 16 + crow]);
        int t11 = __ldg(&ei[NE + ebase + 24 + crow]);

        // ---- Y gather (consumed in epilogue 1) ----
        uint32_t yv[16];
#pragma unroll
        for (int j = 0; j < 4; ++j) {
            int c = (nbase + j * 8 + ccol) >> 1;
            yv[0 * 4 + j] = __ldg(&g_yf16[(size_t)s00 * 64 + c]);
            yv[1 * 4 + j] = __ldg(&g_yf16[(size_t)s01 * 64 + c]);
            yv[2 * 4 + j] = __ldg(&g_yf16[(size_t)s10 * 64 + c]);
            yv[3 * 4 + j] = __ldg(&g_yf16[(size_t)s11 * 64 + c]);
        }

        float acc[2][4][4];
#pragma unroll
        for (int i = 0; i < 2; ++i)
#pragma unroll
            for (int j = 0; j < 4; ++j)
#pragma unroll
                for (int q = 0; q < 4; ++q) acc[i][j][q] = 0.f;

        // ---------- GEMM1': tail[32,48] @ W1t (A from registers) ----------
#pragma unroll
        for (int ks = 0; ks < 3; ++ks) {
            const uint32_t kOff = (uint32_t)(ks * 16) * 2;
#pragma unroll
            for (int jj = 0; jj < 2; ++jj) {
                const uint32_t nOff = (uint32_t)((nbase + jj * 16) * LDAT) * 2;
                uint32_t b[4];
                ldsm_x4(b[0], b[1], b[2], b[3], smb + SM_W1T + b1LaneOff + nOff + kOff);
                mma_f16(acc[0][jj * 2],     &tailA[(0 * 3 + ks) * 4], b);
                mma_f16(acc[0][jj * 2 + 1], &tailA[(0 * 3 + ks) * 4], b + 2);
                mma_f16(acc[1][jj * 2],     &tailA[(1 * 3 + ks) * 4], b);
                mma_f16(acc[1][jj * 2 + 1], &tailA[(1 * 3 + ks) * 4], b + 2);
            }
        }

        // ---- prefetch next tile's tail frags (covered by GEMM2 + barriers) ----
        {
            const int nxt = tile + step;
            if (nxt < NT32) {
                const uint32_t* tf = g_tf16 + (size_t)nxt * EK_M * 24;
#pragma unroll
                for (int mf = 0; mf < 2; ++mf) {
                    int e0 = (mf * 16 + crow) * 24;
                    int e1 = e0 + 8 * 24;
#pragma unroll
                    for (int ks = 0; ks < 3; ++ks) {
                        int o = ks * 8 + kq;
                        tailN[(mf * 3 + ks) * 4 + 0] = __ldg(&tf[e0 + o]);
                        tailN[(mf * 3 + ks) * 4 + 1] = __ldg(&tf[e1 + o]);
                        tailN[(mf * 3 + ks) * 4 + 2] = __ldg(&tf[e0 + o + 4]);
                        tailN[(mf * 3 + ks) * 4 + 3] = __ldg(&tf[e1 + o + 4]);
                    }
                }
            }
        }

        // ---------- epilogue 1: relu(acc + Y + b1) -> H (f16) ----------
#pragma unroll
        for (int mf = 0; mf < 2; ++mf) {
            int r0 = mf * 16 + crow, r1 = r0 + 8;
#pragma unroll
            for (int j = 0; j < 4; ++j) {
                int n = nbase + j * 8 + ccol;
                __half2 y0 = *reinterpret_cast<__half2*>(&yv[(mf * 2 + 0) * 4 + j]);
                __half2 y1 = *reinterpret_cast<__half2*>(&yv[(mf * 2 + 1) * 4 + j]);
                float v0 = fmaxf(acc[mf][j][0] + __low2float(y0)  + b1s[n],     0.f);
                float v1 = fmaxf(acc[mf][j][1] + __high2float(y0) + b1s[n + 1], 0.f);
                float v2 = fmaxf(acc[mf][j][2] + __low2float(y1)  + b1s[n],     0.f);
                float v3 = fmaxf(acc[mf][j][3] + __high2float(y1) + b1s[n + 1], 0.f);
                *(__half2*)(smc + (hBase - smb) + 2 * (r0 * LDH + n)) = __floats2half2_rn(v0, v1);
                *(__half2*)(smc + (hBase - smb) + 2 * (r1 * LDH + n)) = __floats2half2_rn(v2, v3);
            }
        }
        GBAR(barId);

        // ---------- GEMM2: D2 = H(128) @ W2 ----------
#pragma unroll
        for (int i = 0; i < 2; ++i)
#pragma unroll
            for (int j = 0; j < 4; ++j)
#pragma unroll
                for (int q = 0; q < 4; ++q) acc[i][j][q] = 0.f;

#pragma unroll
        for (int ks = 0; ks < 8; ++ks) {
            const uint32_t kOff = (uint32_t)(ks * 16) * 2;
            uint32_t a0[4], a1[4];
            ldsm_x4(a0[0], a0[1], a0[2], a0[3], hBase + hRow0 + kOff);
            ldsm_x4(a1[0], a1[1], a1[2], a1[3], hBase + hRow1 + kOff);
#pragma unroll
            for (int jj = 0; jj < 2; ++jj) {
                const uint32_t nOff = (uint32_t)((nbase + jj * 16) * LDH) * 2;
                uint32_t b[4];
                ldsm_x4(b[0], b[1], b[2], b[3], smb + SM_W2 + b2LaneOff + nOff + kOff);
                mma_f16(acc[0][jj * 2],     a0, b);
                mma_f16(acc[0][jj * 2 + 1], a0, b + 2);
                mma_f16(acc[1][jj * 2],     a1, b);
                mma_f16(acc[1][jj * 2 + 1], a1, b + 2);
            }
        }

        // ---------- epilogue 2: scatter ----------
#pragma unroll
        for (int mf = 0; mf < 2; ++mf) {
            int tg0 = (mf == 0) ? t00 : t10;
            int tg1 = (mf == 0) ? t01 : t11;
            size_t ga0 = __cvta_generic_to_global(&g_agg[(size_t)tg0 * 128]);
            size_t ga1 = __cvta_generic_to_global(&g_agg[(size_t)tg1 * 128]);
#pragma unroll
            for (int j = 0; j < 4; ++j) {
                int n = nbase + j * 8 + ccol;
                float v0 = acc[mf][j][0] + b2s[n];
                float v1 = acc[mf][j][1] + b2s[n + 1];
                float v2 = acc[mf][j][2] + b2s[n];
                float v3 = acc[mf][j][3] + b2s[n + 1];
                asm volatile("red.global.add.v2.f32 [%0], {%1,%2};"
                             :: "l"(ga0 + (size_t)n * 4), "f"(v0), "f"(v1) : "memory");
                asm volatile("red.global.add.v2.f32 [%0], {%1,%2};"
                             :: "l"(ga1 + (size_t)n * 4), "f"(v2), "f"(v3) : "memory");
            }
        }
        GBAR(barId);

#pragma unroll
        for (int i = 0; i < 24; ++i) tailA[i] = tailN[i];
    }
}

// ================= NODE KERNEL (f16-only weights, 2 CTAs/SM) =================
#define NLDB 136
#define NB   0        // [128][136] f16 = 34816
#define NVS  34816    // [64][136]  f16 = 17408
#define NMS  52224    // 17408
#define NODE_SMEM_BYTES 69632

__device__ __forceinline__ void hgemm1_128(uint32_t smb, uint32_t aAddr,
                                           uint32_t bLaneOff, int nbase, float acc[8][4]) {
#pragma unroll
    for (int j = 0; j < 8; ++j)
#pragma unroll
        for (int q = 0; q < 4; ++q) acc[j][q] = 0.f;
#pragma unroll
    for (int ks = 0; ks < 8; ++ks) {
        const uint32_t kOff = (uint32_t)(ks * 16) * 2;
        uint32_t a[4];
        ldsm_x4(a[0], a[1], a[2], a[3], aAddr + kOff);
#pragma unroll
        for (int jj = 0; jj < 4; ++jj) {
            const uint32_t nOff = (uint32_t)((nbase + jj * 16) * NLDB) * 2;
            uint32_t b[4];
            ldsm_x4(b[0], b[1], b[2], b[3], smb + NB + bLaneOff + nOff + kOff);
            mma_f16(acc[2 * jj],     a, b);
            mma_f16(acc[2 * jj + 1], a, b + 2);
        }
    }
}

__device__ __forceinline__ void node_stageB(char* smc, const float* __restrict__ src, int tid) {
    for (int idx = tid; idx < 128 * 64; idx += 256) {
        int n = idx >> 6, kp = idx & 63;
        *(uint32_t*)(smc + NB + 2 * (n * NLDB + 2 * kp)) =
            h2u(__ldg(&src[n * 128 + 2 * kp]), __ldg(&src[n * 128 + 2 * kp + 1]));
    }
}

__global__ __launch_bounds__(256, 2)
void node_kernel(const float* __restrict__ wih, const float* __restrict__ bih,
                 const float* __restrict__ bhh, const float* __restrict__ ow,
                 const float* __restrict__ ob, float* __restrict__ out)
{
    extern __shared__ char smc[];
    const uint32_t smb = smem_u32(smc);
    const int tid = threadIdx.x, wid = tid >> 5, lane = tid & 31;
    const int m0 = (wid & 3) * 16, nbase = (wid >> 2) * 64;
    const int base = blockIdx.x * 64;
    const int crow = lane >> 2, ccol = (lane & 3) * 2;

    for (int idx = tid; idx < 64 * 64; idx += 256) {
        int m = idx >> 6, kp = idx & 63;
        int nd = base + m;
        float a0 = 0.f, a1 = 0.f;
        if (nd < NN) {
            float inv = 1.0f / fmaxf(g_cnt[nd], 1.0f);
            a0 = g_agg[(size_t)nd * 128 + 2 * kp] * inv;
            a1 = g_agg[(size_t)nd * 128 + 2 * kp + 1] * inv;
        }
        *(uint32_t*)(smc + NVS + 2 * (m * NLDB + 2 * kp)) = h2u(a0, a1);
    }

    const uint32_t aRow = (uint32_t)((m0 + (lane & 15)) * NLDB + ((lane >> 4) << 3)) * 2;
    const uint32_t bRow = (uint32_t)((lane & 7) + ((lane >> 4) << 3));
    const uint32_t bLane = (uint32_t)(bRow * NLDB + (((lane >> 3) & 1) << 3)) * 2;

    float acc[8][4], rg[8][4], ng[8][4];

    // ---- r gate ----
    node_stageB(smc, wih, tid);
    __syncthreads();
    hgemm1_128(smb, smb + NVS + aRow, bLane, nbase, acc);
#pragma unroll
    for (int j = 0; j < 8; ++j) {
        int n = nbase + j * 8 + ccol;
        rg[j][0] = sigm(acc[j][0] + __ldg(&bih[n])     + __ldg(&bhh[n]));
        rg[j][1] = sigm(acc[j][1] + __ldg(&bih[n + 1]) + __ldg(&bhh[n + 1]));
        rg[j][2] = sigm(acc[j][2] + __ldg(&bih[n])     + __ldg(&bhh[n]));
        rg[j][3] = sigm(acc[j][3] + __ldg(&bih[n + 1]) + __ldg(&bhh[n + 1]));
    }
    __syncthreads();

    // ---- n gate ----
    node_stageB(smc, wih + 2 * 128 * 128, tid);
    __syncthreads();
    hgemm1_128(smb, smb + NVS + aRow, bLane, nbase, acc);
#pragma unroll
    for (int j = 0; j < 8; ++j) {
        int n = 256 + nbase + j * 8 + ccol;
        ng[j][0] = tanhf(acc[j][0] + __ldg(&bih[n])     + rg[j][0] * __ldg(&bhh[n]));
        ng[j][1] = tanhf(acc[j][1] + __ldg(&bih[n + 1]) + rg[j][1] * __ldg(&bhh[n + 1]));
        ng[j][2] = tanhf(acc[j][2] + __ldg(&bih[n])     + rg[j][2] * __ldg(&bhh[n]));
        ng[j][3] = tanhf(acc[j][3] + __ldg(&bih[n + 1]) + rg[j][3] * __ldg(&bhh[n + 1]));
    }
    __syncthreads();

    // ---- z gate + memory = (1-z)*n ----
    node_stageB(smc, wih + 1 * 128 * 128, tid);
    __syncthreads();
    hgemm1_128(smb, smb + NVS + aRow, bLane, nbase, acc);
    {
        int r0 = m0 + crow, r1 = m0 + crow + 8;
#pragma unroll
        for (int j = 0; j < 8; ++j) {
            int nl = nbase + j * 8 + ccol;
            int n = 128 + nl;
            float z0 = sigm(acc[j][0] + __ldg(&bih[n])     + __ldg(&bhh[n]));
            float z1 = sigm(acc[j][1] + __ldg(&bih[n + 1]) + __ldg(&bhh[n + 1]));
            float z2 = sigm(acc[j][2] + __ldg(&bih[n])     + __ldg(&bhh[n]));
            float z3 = sigm(acc[j][3] + __ldg(&bih[n + 1]) + __ldg(&bhh[n + 1]));
            *(uint32_t*)(smc + NMS + 2 * (r0 * NLDB + nl)) =
                h2u((1.f - z0) * ng[j][0], (1.f - z1) * ng[j][1]);
            *(uint32_t*)(smc + NMS + 2 * (r1 * NLDB + nl)) =
                h2u((1.f - z2) * ng[j][2], (1.f - z3) * ng[j][3]);
        }
    }
    __syncthreads();

    // ---- out projection ----
    node_stageB(smc, ow, tid);
    __syncthreads();
    hgemm1_128(smb, smb + NMS + aRow, bLane, nbase, acc);
    {
        int r0 = m0 + crow, r1 = m0 + crow + 8;
        int nd0 = base + r0, nd1 = base + r1;
#pragma unroll
        for (int j = 0; j < 8; ++j) {
            int n = nbase + j * 8 + ccol;
            float o0 = __ldg(&ob[n]), o1 = __ldg(&ob[n + 1]);
            if (nd0 < NN)
                *(float2*)&out[(size_t)nd0 * 128 + n] = make_float2(acc[j][0] + o0, acc[j][1] + o1);
            if (nd1 < NN)
                *(float2*)&out[(size_t)nd1 * 128 + n] = make_float2(acc[j][2] + o0, acc[j][3] + o1);
        }
    }
}

// ================= launch =================
extern "C" void kernel_launch(void* const* d_in, const int* in_sizes, int n_in,
                              void* d_out, int out_size) {
    const float* x     = (const float*)d_in[0];
    const float* eattr = (const float*)d_in[1];
    const float* t     = (const float*)d_in[2];
    const float* tw    = (const float*)d_in[3];
    const float* tb    = (const float*)d_in[4];
    const float* w1    = (const float*)d_in[5];
    const float* b1    = (const float*)d_in[6];
    const float* w2    = (const float*)d_in[7];
    const float* b2    = (const float*)d_in[8];
    const float* wih   = (const float*)d_in[9];
    const float* bih   = (const float*)d_in[11];
    const float* bhh   = (const float*)d_in[12];
    const float* ow    = (const float*)d_in[13];
    const float* ob    = (const float*)d_in[14];
    const int*   ei    = (const int*)d_in[15];
    float* out = (float*)d_out;

    cudaFuncSetAttribute(edge_kernel, cudaFuncAttributeMaxDynamicSharedMemorySize, EDGE_SMEM_BYTES);
    cudaFuncSetAttribute(node_kernel, cudaFuncAttributeMaxDynamicSharedMemorySize, NODE_SMEM_BYTES);
    cudaFuncSetAttribute(y_kernel,    cudaFuncAttributeMaxDynamicSharedMemorySize, Y_SMEM_BYTES);

    zero_kernel<<<256, 256>>>();
    edge_pre_kernel<<<(NE + 255) / 256, 256>>>(eattr, t, tw, tb, ei);
    y_kernel<<<(NN + 63) / 64, 256, Y_SMEM_BYTES>>>(x, w1);
    edge_kernel<<<148, 384, EDGE_SMEM_BYTES>>>(w1, b1, w2, b2, ei);
    node_kernel<<<(NN + 63) / 64, 256, NODE_SMEM_BYTES>>>(wih, bih, bhh, ow, ob, out);
}